// round 15
// baseline (speedup 1.0000x reference)
#include <cuda_runtime.h>
#include <cstddef>
#include <cstdint>

#define NB 64
#define NT 1024
#define NV 256
#define NS 256
#define ND 24
#define NL 513
#define DGA 1344
#define EMW 260
#define KPH 16          // rows (levels/time-steps) per phase = 8 pairs
#define MLAG_S 3
#define NPH_S 87
#define NPH_C 71
#define STROW 36        // [0..31] data, [32] blank/neighbor-cost, [33] neighbor-em
#define STQ (3 * KPH * STROW)
#define GAMMA 0.1f
#define NEGF (-1e10f)
#define BIGF (1e10f)

__device__ float g_pred[NB * NT * ND];
__device__ float g_cost[(size_t)NB * DGA * NS];
__device__ float g_em[(size_t)NB * NT * EMW];
__device__ float g_loss[2 * NB];

__device__ __forceinline__ float lse2(float a, float b) {
    float m = fmaxf(a, b);
    return m + __logf(1.f + __expf(fminf(a, b) - m));
}
__device__ __forceinline__ float lse3v(float a, float b, float c) {
    float m = fmaxf(a, fmaxf(b, c));
    return m + __logf(__expf(a - m) + __expf(b - m) + __expf(c - m));
}
__device__ __forceinline__ float lse4(float a, float b, float c, float d) {
    float m = fmaxf(fmaxf(a, b), fmaxf(c, d));
    return m + __logf(__expf(a - m) + __expf(b - m) + __expf(c - m) + __expf(d - m));
}
__device__ __forceinline__ float lse5(float a, float b, float c, float d, float e) {
    float m = fmaxf(fmaxf(fmaxf(a, b), fmaxf(c, d)), e);
    return m + __logf(__expf(a - m) + __expf(b - m) + __expf(c - m) +
                      __expf(d - m) + __expf(e - m));
}
__device__ __forceinline__ float smin3(float a, float b, float c) {
    float m = fminf(a, fminf(b, c));
    float s = __expf((m - a) * 10.f) + __expf((m - b) * 10.f) + __expf((m - c) * 10.f);
    return m - GAMMA * __logf(s);
}
__device__ __forceinline__ float smin5(float a, float b, float c, float d, float e) {
    float m = fminf(fminf(a, b), fminf(fminf(c, d), e));
    float s = __expf((m - a) * 10.f) + __expf((m - b) * 10.f) + __expf((m - c) * 10.f) +
              __expf((m - d) * 10.f) + __expf((m - e) * 10.f);
    return m - GAMMA * __logf(s);
}

__device__ __forceinline__ void cpAsync16(uint32_t dst, const void* src) {
    asm volatile("cp.async.cg.shared.global [%0], [%1], 16;" :: "r"(dst), "l"(src));
}
__device__ __forceinline__ void cpAsync4(uint32_t dst, const void* src) {
    asm volatile("cp.async.ca.shared.global [%0], [%1], 4;" :: "r"(dst), "l"(src));
}
__device__ __forceinline__ void cpCommit() { asm volatile("cp.async.commit_group;" ::: "memory"); }
__device__ __forceinline__ void cpWait2() { asm volatile("cp.async.wait_group 2;" ::: "memory"); }

// ---------------- Kernel 1: pred = exp(lp) @ fm ----------------
__global__ __launch_bounds__(256) void prep_kernel(const float* __restrict__ lp,
                                                   const float* __restrict__ fm) {
    __shared__ float eS[64 * 129];
    __shared__ float fmS[64 * 25];
    const int tid = threadIdx.x;
    const int row0 = blockIdx.x * 128;
    const int rg = tid >> 3, dgrp = tid & 7;
    float acc[4][3];
#pragma unroll
    for (int i = 0; i < 4; i++)
#pragma unroll
        for (int j = 0; j < 3; j++) acc[i][j] = 0.f;
    for (int v0 = 0; v0 < NV; v0 += 64) {
        for (int idx = tid; idx < 64 * 24; idx += 256) {
            int v = idx / 24, d = idx - v * 24;
            fmS[v * 25 + d] = fm[(v0 + v) * ND + d];
        }
        for (int idx = tid; idx < 128 * 64; idx += 256) {
            int r = idx >> 6, v = idx & 63;
            eS[v * 129 + r] = __expf(lp[(size_t)(row0 + r) * NV + v0 + v]);
        }
        __syncthreads();
#pragma unroll 4
        for (int v = 0; v < 64; v++) {
            float e0 = eS[v * 129 + rg * 4 + 0], e1 = eS[v * 129 + rg * 4 + 1];
            float e2 = eS[v * 129 + rg * 4 + 2], e3 = eS[v * 129 + rg * 4 + 3];
            float f0 = fmS[v * 25 + dgrp * 3 + 0], f1 = fmS[v * 25 + dgrp * 3 + 1];
            float f2 = fmS[v * 25 + dgrp * 3 + 2];
            acc[0][0] += e0 * f0; acc[0][1] += e0 * f1; acc[0][2] += e0 * f2;
            acc[1][0] += e1 * f0; acc[1][1] += e1 * f1; acc[1][2] += e1 * f2;
            acc[2][0] += e2 * f0; acc[2][1] += e2 * f1; acc[2][2] += e2 * f2;
            acc[3][0] += e3 * f0; acc[3][1] += e3 * f1; acc[3][2] += e3 * f2;
        }
        __syncthreads();
    }
#pragma unroll
    for (int i = 0; i < 4; i++)
#pragma unroll
        for (int j = 0; j < 3; j++)
            g_pred[(size_t)(row0 + rg * 4 + i) * ND + dgrp * 3 + j] = acc[i][j];
}

// ---------------- Kernel 2: cost matrix [b][dg][j] ----------------
__global__ __launch_bounds__(256) void cost_kernel(const float* __restrict__ fm,
                                                   const int* __restrict__ targets) {
    __shared__ float predS[64 * 25];
    __shared__ float qS[256 * 25];
    __shared__ float pn[64];
    __shared__ float qn[256];
    __shared__ int qlab[256];
    const int tid = threadIdx.x;
    const int b = blockIdx.y;
    const int i0 = blockIdx.x * 64;
    qlab[tid] = targets[b * NS + tid];
    for (int idx = tid; idx < 64 * 24; idx += 256)
        predS[(idx / 24) * 25 + (idx % 24)] = g_pred[(size_t)(b * NT + i0) * ND + idx];
    __syncthreads();
    for (int idx = tid; idx < 256 * 24; idx += 256) {
        int c = idx / 24, d = idx - c * 24;
        qS[c * 25 + d] = fm[qlab[c] * ND + d];
    }
    __syncthreads();
    if (tid < 64) {
        float s = 0.f;
#pragma unroll
        for (int d = 0; d < ND; d++) { float x = predS[tid * 25 + d]; s += x * x; }
        pn[tid] = s;
    }
    {
        float s = 0.f;
#pragma unroll
        for (int d = 0; d < ND; d++) { float x = qS[tid * 25 + d]; s += x * x; }
        qn[tid] = s;
    }
    __syncthreads();
    const int w = tid >> 5, lane = tid & 31, j0 = w * 32;
    float p0[ND], p1[ND];
#pragma unroll
    for (int k = 0; k < ND; k++) {
        p0[k] = predS[lane * 25 + k];
        p1[k] = predS[(lane + 32) * 25 + k];
    }
    const float pn0 = pn[lane], pn1 = pn[lane + 32];
    const size_t cb = (size_t)b * DGA;
    const int D0 = i0 + j0 + 2;
#pragma unroll 4
    for (int c = 0; c < 32; c++) {
        int jc = j0 + ((c - lane) & 31);
        float dot0 = 0.f, dot1 = 0.f;
#pragma unroll
        for (int k = 0; k < ND; k++) {
            float q = qS[jc * 25 + k];
            dot0 += p0[k] * q;
            dot1 += p1[k] * q;
        }
        float qnj = qn[jc];
        int dg0 = D0 + c + ((lane > c) ? 32 : 0);
        g_cost[(cb + dg0) * NS + jc] = pn0 + qnj - 2.f * dot0;
        g_cost[(cb + dg0 + 32) * NS + jc] = pn1 + qnj - 2.f * dot1;
    }
}

// ---------------- Kernel 3: emissions ----------------
__global__ __launch_bounds__(256) void em_kernel(const float* __restrict__ lp,
                                                 const int* __restrict__ targets) {
    __shared__ float rowS[4][256];
    __shared__ int tgtS[256];
    const int tid = threadIdx.x;
    const int b = blockIdx.x >> 4;
    const int t0 = (blockIdx.x & 15) << 6;
    tgtS[tid] = targets[b * NS + tid];
    const float* lpb = lp + ((size_t)b * NT + t0) * NV;
    float* emb = g_em + ((size_t)b * NT + t0) * EMW;
    __syncthreads();
    for (int tt = 0; tt < 64; tt += 4) {
#pragma unroll
        for (int r = 0; r < 4; r++)
            rowS[r][tid] = lpb[(size_t)(tt + r) * NV + tid];
        __syncthreads();
#pragma unroll
        for (int r = 0; r < 4; r++)
            emb[(size_t)(tt + r) * EMW + tid] = rowS[r][tgtS[tid]];
        if (tid < 4) emb[(size_t)(tt + tid) * EMW + 256] = rowS[tid][0];
        __syncthreads();
    }
}

// ---------------- Kernel 4: fused DP, 2-step semiring composition ----------------
extern __shared__ float smf[];

__global__ __launch_bounds__(256) void main_kernel(const int* __restrict__ targets,
                                                   const int* __restrict__ in_len,
                                                   const int* __restrict__ tg_len) {
    float* stage = smf;                                  // [8][3][KPH][STROW]
    const int tid = threadIdx.x;
    const int lane = tid & 31;
    const int w = tid >> 5;
    const int bid = blockIdx.x;
    const int wp = (w == 0) ? 0 : (w - 1);

    const uint32_t stageU =
        (uint32_t)__cvta_generic_to_shared(stage) + (uint32_t)(w * STQ) * 4u;
    const int rsel = lane >> 3;
    const int csel = lane & 7;

    if (bid < NB) {
        // =============== soft-DTW (pairs of diagonals) ===============
        float* ringS = smf + 8 * STQ;                    // [8][64][4]
        const int b = bid;
        const int s0 = 32 * w + 2;
        const int jj = tid + 1;

        auto stageS = [&](int buf, int dgStart) {
#pragma unroll
            for (int r = 0; r < 4; r++) {
                int row = 4 * r + rsel;
                int dgr = dgStart + row;
                dgr = (dgr < 0) ? 0 : ((dgr > DGA - 1) ? DGA - 1 : dgr);
                uint32_t off = (uint32_t)((buf * KPH + row) * STROW + csel * 4) * 4u;
                cpAsync16(stageU + off,
                          g_cost + ((size_t)b * DGA + dgr) * NS + 32 * w + csel * 4);
            }
            if (lane >= 16) {                            // neighbor cost col 32w-1
                int row = lane - 16;
                int dgr = dgStart + row;
                dgr = (dgr < 0) ? 0 : ((dgr > DGA - 1) ? DGA - 1 : dgr);
                int nc = (w == 0) ? 0 : (32 * w - 1);
                cpAsync4(stageU + (uint32_t)((buf * KPH + row) * STROW + 32) * 4u,
                         g_cost + ((size_t)b * DGA + dgr) * NS + nc);
            }
            cpCommit();
        };

        stageS(0, s0 + (0 - MLAG_S * w) * KPH);
        stageS(1, s0 + (1 - MLAG_S * w) * KPH);
        __syncthreads();

        float E = BIGF, O = BIGF;   // R[.,D-2], R[.,D-1] entering each pair

        int buf = 0;
        for (int p = 0; p < NPH_S; p++) {
            int bufN = buf + 2; if (bufN >= 3) bufN -= 3;
            stageS(bufN, s0 + (p + 2 - MLAG_S * w) * KPH);
            cpWait2();
            __syncwarp();
            const int prel = p - MLAG_S * w;
            if (prel >= 0 && prel <= 65) {
                const int Dbase = s0 + prel * KPH;
                const float* rowB = stage + w * STQ + buf * KPH * STROW;
                float cc0[8], cc1[8], cdm[8], cpd[8], w2[8];
                float rOq[8], rEq[8], sOq[8], sEq[8];
#pragma unroll
                for (int q = 0; q < 8; q++) {
                    int Dq = Dbase + 2 * q;
                    float c0 = rowB[(2 * q) * STROW + lane];
                    float c1 = rowB[(2 * q + 1) * STROW + lane];
                    float cn = __shfl_up_sync(0xffffffffu, c0, 1);
                    if (lane == 0) cn = rowB[(2 * q) * STROW + 32];
                    int i0 = Dq - jj;
                    float Cd = (i0 >= 1 && i0 <= NT) ? c0 : BIGF;
                    cc0[q] = c0; cc1[q] = c1; cdm[q] = Cd; cpd[q] = cn;
                    w2[q] = smin3(Cd, cn, 0.f);
                    int pid = (Dq - 2) >> 1;
                    const float* rg = ringS + ((size_t)wp * 64 + ((pid - 1) & 63)) * 4;
                    rEq[q] = rg[0]; rOq[q] = rg[1]; sEq[q] = rg[2]; sOq[q] = rg[3];
                }
#pragma unroll
                for (int q = 0; q < 8; q++) {
                    const int Dq = Dbase + 2 * q;
                    float bE = (Dq == 2) ? 0.f : BIGF;
                    float pO = __shfl_up_sync(0xffffffffu, O, 1);
                    float pE = __shfl_up_sync(0xffffffffu, E, 1);
                    float qO = __shfl_up_sync(0xffffffffu, O, 2);
                    float qE = __shfl_up_sync(0xffffffffu, E, 2);
                    if (lane == 0) {
                        pO = w ? rOq[q] : BIGF;
                        pE = w ? rEq[q] : bE;
                        qO = w ? sOq[q] : BIGF;
                        qE = w ? sEq[q] : BIGF;
                    }
                    if (lane == 1) {
                        qO = w ? rOq[q] : BIGF;
                        qE = w ? rEq[q] : bE;
                    }
                    const int i0 = Dq - jj;
                    float X = cc0[q] + smin3(O, pO, pE);
                    X = (i0 >= 1 && i0 <= NT) ? X : BIGF;
                    float Y = cc1[q] + smin5(O + cdm[q], pO + w2[q], pE + cdm[q],
                                             qO + cpd[q], qE + cpd[q]);
                    Y = (i0 >= 0 && i0 <= NT - 1) ? Y : BIGF;
                    if (lane >= 30) {
                        float* rg = ringS + ((size_t)w * 64 + (((Dq - 2) >> 1) & 63)) * 4
                                    + ((lane == 31) ? 0 : 2);
                        rg[0] = X; rg[1] = Y;
                    }
                    if (tid == 255 && Dq == NT + NS) g_loss[NB + b] = X;
                    E = X; O = Y;
                }
            }
            buf++; if (buf >= 3) buf -= 3;
            __syncthreads();
        }
    } else {
        // =============== CTC forward (pairs of time steps) ===============
        float* ringC = smf + 8 * STQ;                    // [8][32][4]
        float* actc = ringC + 8 * 32 * 4;                // [513]
        const int b = bid - NB;
        bool sk = false, skp = false;
        if (tid > 0) sk = (targets[b * NS + tid] != targets[b * NS + tid - 1]);
        if (tid > 1) skp = (targets[b * NS + tid - 1] != targets[b * NS + tid - 2]);
        const float* em = g_em + (size_t)b * NT * EMW;
        const int len = in_len[b];

        auto stageC = [&](int buf, int tStart) {
#pragma unroll
            for (int r = 0; r < 4; r++) {
                int row = 4 * r + rsel;
                int tr = tStart + row;
                tr = (tr < 0) ? 0 : ((tr > NT - 1) ? NT - 1 : tr);
                uint32_t off = (uint32_t)((buf * KPH + row) * STROW + csel * 4) * 4u;
                cpAsync16(stageU + off, em + (size_t)tr * EMW + 32 * w + csel * 4);
            }
            {
                int row = lane & 15;
                int tr = tStart + row;
                tr = (tr < 0) ? 0 : ((tr > NT - 1) ? NT - 1 : tr);
                if (lane < 16)       // blank
                    cpAsync4(stageU + (uint32_t)((buf * KPH + row) * STROW + 32) * 4u,
                             em + (size_t)tr * EMW + 256);
                else {               // neighbor label 32w-1
                    int nc = (w == 0) ? 0 : (32 * w - 1);
                    cpAsync4(stageU + (uint32_t)((buf * KPH + row) * STROW + 33) * 4u,
                             em + (size_t)tr * EMW + nc);
                }
            }
            cpCommit();
        };

        stageC(0, 1 + (0 - w) * KPH);
        stageC(1, 1 + (1 - w) * KPH);

        float A0 = NEGF, A1 = NEGF, A4 = NEGF;
        if (tid == 0) { A0 = em[256]; A1 = em[0]; }
        if (lane >= 30) {
            float* rg = ringC + (size_t)w * 32 * 4;
            if (lane == 31) { rg[0] = A0; rg[1] = A1; }
            else rg[2] = A1;
        }
        __syncthreads();

        int buf = 0;
        for (int p = 0; p < NPH_C; p++) {
            int bufN = buf + 2; if (bufN >= 3) bufN -= 3;
            stageC(bufN, 1 + (p + 2 - w) * KPH);
            cpWait2();
            __syncwarp();
            const int tB = 1 + (p - w) * KPH;
            if (p >= w && tB < len) {
                const float* rowB = stage + w * STQ + buf * KPH * STROW;
                float eeA[8], eeB[8], ebA[8], ebB[8], peA[8], wP[8], wR[8], wS[8];
                float rA0[8], rA1[8], rB1[8];
#pragma unroll
                for (int q = 0; q < 8; q++) {
                    float e0 = rowB[(2 * q) * STROW + lane];
                    float e1 = rowB[(2 * q + 1) * STROW + lane];
                    float b0 = rowB[(2 * q) * STROW + 32];
                    float b1 = rowB[(2 * q + 1) * STROW + 32];
                    float pe = __shfl_up_sync(0xffffffffu, e0, 1);
                    if (lane == 0) pe = rowB[(2 * q) * STROW + 33];
                    eeA[q] = e0; eeB[q] = e1; ebA[q] = b0; ebB[q] = b1; peA[q] = pe;
                    wP[q] = lse2(b0, pe);
                    wR[q] = lse2(e0, b0);
                    wS[q] = lse3v(sk ? e0 : NEGF, b0, sk ? pe : NEGF);
                    int slot = (((tB - 1) >> 1) + q) & 31;
                    const float* rg = ringC + ((size_t)wp * 32 + slot) * 4;
                    rA0[q] = rg[0]; rA1[q] = rg[1]; rB1[q] = rg[2];
                }
#pragma unroll
                for (int q = 0; q < 8; q++) {
                    const int t = tB + 2 * q;
                    float p1 = __shfl_up_sync(0xffffffffu, A1, 1);
                    float p0 = __shfl_up_sync(0xffffffffu, A0, 1);
                    float q1s = __shfl_up_sync(0xffffffffu, A1, 2);
                    if (lane == 0) {
                        p1 = w ? rA1[q] : NEGF;
                        p0 = w ? rA0[q] : NEGF;
                        q1s = w ? rB1[q] : NEGF;
                    }
                    if (lane == 1) q1s = w ? rA1[q] : NEGF;
                    if (t + 1 < len) {
                        float n0 = lse4(A0 + ebA[q], p1 + wP[q], p0 + peA[q],
                                        skp ? (q1s + peA[q]) : NEGF) + ebB[q];
                        float n1 = lse5(A1 + eeA[q], A0 + wR[q], p1 + wS[q],
                                        sk ? (p0 + peA[q]) : NEGF,
                                        (sk && skp) ? (q1s + peA[q]) : NEGF) + eeB[q];
                        if (w == 7) {
                            float n4 = lse4(A4 + ebA[q], A1 + wR[q], A0 + eeA[q],
                                            sk ? (p1 + eeA[q]) : NEGF) + ebB[q];
                            A4 = (lane == 31) ? n4 : A4;
                        }
                        if (lane >= 30) {
                            float* rg = ringC + ((size_t)w * 32 + (((t + 1) >> 1) & 31)) * 4;
                            if (lane == 31) { rg[0] = n0; rg[1] = n1; }
                            else rg[2] = n1;
                        }
                        A0 = n0; A1 = n1;
                    } else if (t < len) {
                        float n0 = lse2(A0, p1) + ebA[q];
                        float n1 = lse3v(A1, A0, sk ? p1 : NEGF) + eeA[q];
                        if (w == 7) {
                            float n4 = lse2(A4, A1) + ebA[q];
                            A4 = (lane == 31) ? n4 : A4;
                        }
                        A0 = n0; A1 = n1;
                    }
                }
            }
            buf++; if (buf >= 3) buf -= 3;
            __syncthreads();
        }

        actc[2 * tid + 0] = A0;
        actc[2 * tid + 1] = A1;
        if (tid == 255) actc[512] = A4;
        __syncthreads();
        if (tid == 0) {
            int tl = tg_len[b];
            float aL = actc[2 * tl];
            float aP = actc[2 * tl - 1];
            float m = fmaxf(aL, aP);
            float ll = m + __logf(__expf(aL - m) + __expf(aP - m));
            g_loss[b] = -ll / (float)tl;
        }
    }
}

// ---------------- Kernel 5: reduction ----------------
__global__ void reduce_kernel(float* __restrict__ out) {
    const int tid = threadIdx.x;
    float v = g_loss[tid];
#pragma unroll
    for (int o = 16; o > 0; o >>= 1) v += __shfl_down_sync(0xffffffffu, v, o);
    __shared__ float ws[4];
    if ((tid & 31) == 0) ws[tid >> 5] = v;
    __syncthreads();
    if (tid == 0) out[0] = (ws[0] + ws[1] + ws[2] + ws[3]) * (1.f / (float)NB);
}

extern "C" void kernel_launch(void* const* d_in, const int* in_sizes, int n_in,
                              void* d_out, int out_size) {
    const float* lp  = (const float*)d_in[0];
    const float* fm  = (const float*)d_in[1];
    const int*   tgt = (const int*)  d_in[2];
    const int*   il  = (const int*)  d_in[3];
    const int*   tl  = (const int*)  d_in[4];
    float* out = (float*)d_out;

    // stage 8*STQ + ringS 8*64*4 (sdtw) / ringC 8*32*4 + actc (ctc) floats
    const int dynSmem = (8 * STQ + 8 * 64 * 4) * 4;   // 63,488 B
    cudaFuncSetAttribute(main_kernel, cudaFuncAttributeMaxDynamicSharedMemorySize, dynSmem);

    prep_kernel<<<512, 256>>>(lp, fm);
    em_kernel<<<1024, 256>>>(lp, tgt);
    cost_kernel<<<dim3(16, 64), 256>>>(fm, tgt);
    main_kernel<<<2 * NB, 256, dynSmem>>>(tgt, il, tl);
    reduce_kernel<<<1, 128>>>(out);
}

// round 16
// speedup vs baseline: 1.0359x; 1.0359x over previous
#include <cuda_runtime.h>
#include <cstddef>
#include <cstdint>

#define NB 64
#define NT 1024
#define NV 256
#define NS 256
#define ND 24
#define NL 513
#define DGA 1344
#define EMW 260
#define KPH 8           // rows (levels/time-steps) per phase = 4 pairs
#define MLAG_S 5        // (m*8 >= 8+31)
#define NPH_S 167       // 132 active + 5*7 lag
#define NPH_C 135       // 128 active + 7 lag
#define STROW 36        // [0..31] data, [32] blank/neighbor-cost, [33] neighbor-em
#define STQ (3 * KPH * STROW)   // 864 floats per warp
#define GAMMA 0.1f
#define NEGF (-1e10f)
#define BIGF (1e10f)

__device__ float g_pred[NB * NT * ND];
__device__ float g_cost[(size_t)NB * DGA * NS];
__device__ float g_em[(size_t)NB * NT * EMW];
__device__ float g_loss[2 * NB];

__device__ __forceinline__ float lse2(float a, float b) {
    float m = fmaxf(a, b);
    return m + __logf(1.f + __expf(fminf(a, b) - m));
}
__device__ __forceinline__ float lse3v(float a, float b, float c) {
    float m = fmaxf(a, fmaxf(b, c));
    return m + __logf(__expf(a - m) + __expf(b - m) + __expf(c - m));
}
__device__ __forceinline__ float lse4(float a, float b, float c, float d) {
    float m = fmaxf(fmaxf(a, b), fmaxf(c, d));
    return m + __logf(__expf(a - m) + __expf(b - m) + __expf(c - m) + __expf(d - m));
}
__device__ __forceinline__ float lse5(float a, float b, float c, float d, float e) {
    float m = fmaxf(fmaxf(fmaxf(a, b), fmaxf(c, d)), e);
    return m + __logf(__expf(a - m) + __expf(b - m) + __expf(c - m) +
                      __expf(d - m) + __expf(e - m));
}
__device__ __forceinline__ float smin3(float a, float b, float c) {
    float m = fminf(a, fminf(b, c));
    float s = __expf((m - a) * 10.f) + __expf((m - b) * 10.f) + __expf((m - c) * 10.f);
    return m - GAMMA * __logf(s);
}
__device__ __forceinline__ float smin5(float a, float b, float c, float d, float e) {
    float m = fminf(fminf(a, b), fminf(fminf(c, d), e));
    float s = __expf((m - a) * 10.f) + __expf((m - b) * 10.f) + __expf((m - c) * 10.f) +
              __expf((m - d) * 10.f) + __expf((m - e) * 10.f);
    return m - GAMMA * __logf(s);
}

__device__ __forceinline__ void cpAsync16(uint32_t dst, const void* src) {
    asm volatile("cp.async.cg.shared.global [%0], [%1], 16;" :: "r"(dst), "l"(src));
}
__device__ __forceinline__ void cpAsync4(uint32_t dst, const void* src) {
    asm volatile("cp.async.ca.shared.global [%0], [%1], 4;" :: "r"(dst), "l"(src));
}
__device__ __forceinline__ void cpCommit() { asm volatile("cp.async.commit_group;" ::: "memory"); }
__device__ __forceinline__ void cpWait2() { asm volatile("cp.async.wait_group 2;" ::: "memory"); }

// ---------------- Kernel 1: pred = exp(lp) @ fm ----------------
__global__ __launch_bounds__(256) void prep_kernel(const float* __restrict__ lp,
                                                   const float* __restrict__ fm) {
    __shared__ float eS[64 * 129];
    __shared__ float fmS[64 * 25];
    const int tid = threadIdx.x;
    const int row0 = blockIdx.x * 128;
    const int rg = tid >> 3, dgrp = tid & 7;
    float acc[4][3];
#pragma unroll
    for (int i = 0; i < 4; i++)
#pragma unroll
        for (int j = 0; j < 3; j++) acc[i][j] = 0.f;
    for (int v0 = 0; v0 < NV; v0 += 64) {
        for (int idx = tid; idx < 64 * 24; idx += 256) {
            int v = idx / 24, d = idx - v * 24;
            fmS[v * 25 + d] = fm[(v0 + v) * ND + d];
        }
        for (int idx = tid; idx < 128 * 64; idx += 256) {
            int r = idx >> 6, v = idx & 63;
            eS[v * 129 + r] = __expf(lp[(size_t)(row0 + r) * NV + v0 + v]);
        }
        __syncthreads();
#pragma unroll 4
        for (int v = 0; v < 64; v++) {
            float e0 = eS[v * 129 + rg * 4 + 0], e1 = eS[v * 129 + rg * 4 + 1];
            float e2 = eS[v * 129 + rg * 4 + 2], e3 = eS[v * 129 + rg * 4 + 3];
            float f0 = fmS[v * 25 + dgrp * 3 + 0], f1 = fmS[v * 25 + dgrp * 3 + 1];
            float f2 = fmS[v * 25 + dgrp * 3 + 2];
            acc[0][0] += e0 * f0; acc[0][1] += e0 * f1; acc[0][2] += e0 * f2;
            acc[1][0] += e1 * f0; acc[1][1] += e1 * f1; acc[1][2] += e1 * f2;
            acc[2][0] += e2 * f0; acc[2][1] += e2 * f1; acc[2][2] += e2 * f2;
            acc[3][0] += e3 * f0; acc[3][1] += e3 * f1; acc[3][2] += e3 * f2;
        }
        __syncthreads();
    }
#pragma unroll
    for (int i = 0; i < 4; i++)
#pragma unroll
        for (int j = 0; j < 3; j++)
            g_pred[(size_t)(row0 + rg * 4 + i) * ND + dgrp * 3 + j] = acc[i][j];
}

// ---------------- Kernel 2: cost matrix [b][dg][j] ----------------
__global__ __launch_bounds__(256) void cost_kernel(const float* __restrict__ fm,
                                                   const int* __restrict__ targets) {
    __shared__ float predS[64 * 25];
    __shared__ float qS[256 * 25];
    __shared__ float pn[64];
    __shared__ float qn[256];
    __shared__ int qlab[256];
    const int tid = threadIdx.x;
    const int b = blockIdx.y;
    const int i0 = blockIdx.x * 64;
    qlab[tid] = targets[b * NS + tid];
    for (int idx = tid; idx < 64 * 24; idx += 256)
        predS[(idx / 24) * 25 + (idx % 24)] = g_pred[(size_t)(b * NT + i0) * ND + idx];
    __syncthreads();
    for (int idx = tid; idx < 256 * 24; idx += 256) {
        int c = idx / 24, d = idx - c * 24;
        qS[c * 25 + d] = fm[qlab[c] * ND + d];
    }
    __syncthreads();
    if (tid < 64) {
        float s = 0.f;
#pragma unroll
        for (int d = 0; d < ND; d++) { float x = predS[tid * 25 + d]; s += x * x; }
        pn[tid] = s;
    }
    {
        float s = 0.f;
#pragma unroll
        for (int d = 0; d < ND; d++) { float x = qS[tid * 25 + d]; s += x * x; }
        qn[tid] = s;
    }
    __syncthreads();
    const int w = tid >> 5, lane = tid & 31, j0 = w * 32;
    float p0[ND], p1[ND];
#pragma unroll
    for (int k = 0; k < ND; k++) {
        p0[k] = predS[lane * 25 + k];
        p1[k] = predS[(lane + 32) * 25 + k];
    }
    const float pn0 = pn[lane], pn1 = pn[lane + 32];
    const size_t cb = (size_t)b * DGA;
    const int D0 = i0 + j0 + 2;
#pragma unroll 4
    for (int c = 0; c < 32; c++) {
        int jc = j0 + ((c - lane) & 31);
        float dot0 = 0.f, dot1 = 0.f;
#pragma unroll
        for (int k = 0; k < ND; k++) {
            float q = qS[jc * 25 + k];
            dot0 += p0[k] * q;
            dot1 += p1[k] * q;
        }
        float qnj = qn[jc];
        int dg0 = D0 + c + ((lane > c) ? 32 : 0);
        g_cost[(cb + dg0) * NS + jc] = pn0 + qnj - 2.f * dot0;
        g_cost[(cb + dg0 + 32) * NS + jc] = pn1 + qnj - 2.f * dot1;
    }
}

// ---------------- Kernel 3: emissions ----------------
__global__ __launch_bounds__(256) void em_kernel(const float* __restrict__ lp,
                                                 const int* __restrict__ targets) {
    __shared__ float rowS[4][256];
    __shared__ int tgtS[256];
    const int tid = threadIdx.x;
    const int b = blockIdx.x >> 4;
    const int t0 = (blockIdx.x & 15) << 6;
    tgtS[tid] = targets[b * NS + tid];
    const float* lpb = lp + ((size_t)b * NT + t0) * NV;
    float* emb = g_em + ((size_t)b * NT + t0) * EMW;
    __syncthreads();
    for (int tt = 0; tt < 64; tt += 4) {
#pragma unroll
        for (int r = 0; r < 4; r++)
            rowS[r][tid] = lpb[(size_t)(tt + r) * NV + tid];
        __syncthreads();
#pragma unroll
        for (int r = 0; r < 4; r++)
            emb[(size_t)(tt + r) * EMW + tid] = rowS[r][tgtS[tid]];
        if (tid < 4) emb[(size_t)(tt + tid) * EMW + 256] = rowS[tid][0];
        __syncthreads();
    }
}

// ---------------- Kernel 4: fused DP, lean 2-step semiring composition ----------------
extern __shared__ float smf[];

__global__ __launch_bounds__(256) void main_kernel(const int* __restrict__ targets,
                                                   const int* __restrict__ in_len,
                                                   const int* __restrict__ tg_len) {
    float* stage = smf;                                  // [8][3][KPH][STROW]
    const int tid = threadIdx.x;
    const int lane = tid & 31;
    const int w = tid >> 5;
    const int bid = blockIdx.x;
    const int wp = (w == 0) ? 0 : (w - 1);

    const uint32_t stageU =
        (uint32_t)__cvta_generic_to_shared(stage) + (uint32_t)(w * STQ) * 4u;
    const int rsel = lane >> 3;            // 0..3
    const int csel = lane & 7;             // 0..7

    if (bid < NB) {
        // =============== soft-DTW (pairs of diagonals) ===============
        float* ringS = smf + 8 * STQ;                    // [8][64][4]
        const int b = bid;
        const int s0 = 32 * w + 2;
        const int jj = tid + 1;

        auto stageS = [&](int buf, int dgStart) {
#pragma unroll
            for (int r = 0; r < 2; r++) {
                int row = 4 * r + rsel;                  // 0..7
                int dgr = dgStart + row;
                dgr = (dgr < 0) ? 0 : ((dgr > DGA - 1) ? DGA - 1 : dgr);
                uint32_t off = (uint32_t)((buf * KPH + row) * STROW + csel * 4) * 4u;
                cpAsync16(stageU + off,
                          g_cost + ((size_t)b * DGA + dgr) * NS + 32 * w + csel * 4);
            }
            if (lane >= 16 && lane < 24) {               // neighbor cost col 32w-1
                int row = lane - 16;
                int dgr = dgStart + row;
                dgr = (dgr < 0) ? 0 : ((dgr > DGA - 1) ? DGA - 1 : dgr);
                int nc = (w == 0) ? 0 : (32 * w - 1);
                cpAsync4(stageU + (uint32_t)((buf * KPH + row) * STROW + 32) * 4u,
                         g_cost + ((size_t)b * DGA + dgr) * NS + nc);
            }
            cpCommit();
        };

        stageS(0, s0 + (0 - MLAG_S * w) * KPH);
        stageS(1, s0 + (1 - MLAG_S * w) * KPH);
        __syncthreads();

        float E = BIGF, O = BIGF;   // R[.,D-2], R[.,D-1] entering each pair

        int buf = 0;
        for (int p = 0; p < NPH_S; p++) {
            int bufN = buf + 2; if (bufN >= 3) bufN -= 3;
            stageS(bufN, s0 + (p + 2 - MLAG_S * w) * KPH);
            cpWait2();
            __syncwarp();
            const int prel = p - MLAG_S * w;
            if (prel >= 0 && prel <= 131) {
                const int Dbase = s0 + prel * KPH;
                const float* rowB = stage + w * STQ + buf * KPH * STROW;
                float cc1[4], cdm[4], cpd[4], w2[4];
#pragma unroll
                for (int q = 0; q < 4; q++) {
                    int Dq = Dbase + 2 * q;
                    float c0 = rowB[(2 * q) * STROW + lane];
                    cc1[q] = rowB[(2 * q + 1) * STROW + lane];
                    float cn = __shfl_up_sync(0xffffffffu, c0, 1);
                    if (lane == 0) cn = rowB[(2 * q) * STROW + 32];
                    int i0 = Dq - jj;
                    float Cd = (i0 >= 1 && i0 <= NT) ? c0 : BIGF;
                    cdm[q] = Cd; cpd[q] = cn;
                    w2[q] = smin3(Cd, cn, 0.f);
                }
#pragma unroll
                for (int q = 0; q < 4; q++) {
                    const int Dq = Dbase + 2 * q;
                    const float bE = (Dq == 2) ? 0.f : BIGF;
                    float pO = __shfl_up_sync(0xffffffffu, O, 1);
                    float pE = __shfl_up_sync(0xffffffffu, E, 1);
                    float qO = __shfl_up_sync(0xffffffffu, O, 2);
                    float qE = __shfl_up_sync(0xffffffffu, E, 2);
                    const int pid = (Dq - 2) >> 1;
                    const float* rg = ringS + ((size_t)wp * 64 + ((pid - 1) & 63)) * 4;
                    float rE = rg[0], rO = rg[1], sE = rg[2], sO = rg[3];  // broadcast
                    if (lane == 0) {
                        pO = w ? rO : BIGF;
                        pE = w ? rE : bE;
                        qO = w ? sO : BIGF;
                        qE = w ? sE : BIGF;
                    }
                    if (lane == 1) {
                        qO = w ? rO : BIGF;
                        qE = w ? rE : bE;
                    }
                    const int i0 = Dq - jj;
                    float X = cdm[q] + smin3(O, pO, pE);
                    X = (i0 >= 1 && i0 <= NT) ? X : BIGF;
                    float Y = cc1[q] + smin5(O + cdm[q], pO + w2[q], pE + cdm[q],
                                             qO + cpd[q], qE + cpd[q]);
                    Y = (i0 >= 0 && i0 <= NT - 1) ? Y : BIGF;
                    if (lane >= 30) {
                        float* rw = ringS + ((size_t)w * 64 + (pid & 63)) * 4
                                    + ((lane == 31) ? 0 : 2);
                        rw[0] = X; rw[1] = Y;
                    }
                    if (tid == 255 && Dq == NT + NS) g_loss[NB + b] = X;
                    E = X; O = Y;
                }
            }
            buf++; if (buf >= 3) buf -= 3;
            __syncthreads();
        }
    } else {
        // =============== CTC forward (pairs of time steps) ===============
        float* ringC = smf + 8 * STQ;                    // [8][32][4]
        float* actc = ringC + 8 * 32 * 4;                // [513]
        const int b = bid - NB;
        bool sk = false, skp = false;
        if (tid > 0) sk = (targets[b * NS + tid] != targets[b * NS + tid - 1]);
        if (tid > 1) skp = (targets[b * NS + tid - 1] != targets[b * NS + tid - 2]);
        const float* em = g_em + (size_t)b * NT * EMW;
        const int len = in_len[b];

        auto stageC = [&](int buf, int tStart) {
#pragma unroll
            for (int r = 0; r < 2; r++) {
                int row = 4 * r + rsel;
                int tr = tStart + row;
                tr = (tr < 0) ? 0 : ((tr > NT - 1) ? NT - 1 : tr);
                uint32_t off = (uint32_t)((buf * KPH + row) * STROW + csel * 4) * 4u;
                cpAsync16(stageU + off, em + (size_t)tr * EMW + 32 * w + csel * 4);
            }
            if (lane < 8) {                              // blank
                int tr = tStart + lane;
                tr = (tr < 0) ? 0 : ((tr > NT - 1) ? NT - 1 : tr);
                cpAsync4(stageU + (uint32_t)((buf * KPH + lane) * STROW + 32) * 4u,
                         em + (size_t)tr * EMW + 256);
            } else if (lane >= 16 && lane < 24) {        // neighbor label 32w-1
                int row = lane - 16;
                int tr = tStart + row;
                tr = (tr < 0) ? 0 : ((tr > NT - 1) ? NT - 1 : tr);
                int nc = (w == 0) ? 0 : (32 * w - 1);
                cpAsync4(stageU + (uint32_t)((buf * KPH + row) * STROW + 33) * 4u,
                         em + (size_t)tr * EMW + nc);
            }
            cpCommit();
        };

        stageC(0, 1 + (0 - w) * KPH);
        stageC(1, 1 + (1 - w) * KPH);

        float A0 = NEGF, A1 = NEGF, A4 = NEGF;
        if (tid == 0) { A0 = em[256]; A1 = em[0]; }
        if (lane >= 30) {
            float* rw = ringC + (size_t)w * 32 * 4;
            if (lane == 31) { rw[0] = A0; rw[1] = A1; }
            else rw[2] = A1;
        }
        __syncthreads();

        int buf = 0;
        for (int p = 0; p < NPH_C; p++) {
            int bufN = buf + 2; if (bufN >= 3) bufN -= 3;
            stageC(bufN, 1 + (p + 2 - w) * KPH);
            cpWait2();
            __syncwarp();
            const int tB = 1 + (p - w) * KPH;
            if (p >= w && tB < len) {
                const float* rowB = stage + w * STQ + buf * KPH * STROW;
                float eeA[4], eeB[4], ebA[4], ebB[4], peA[4], wP[4], wR[4], wS[4];
#pragma unroll
                for (int q = 0; q < 4; q++) {
                    float e0 = rowB[(2 * q) * STROW + lane];
                    eeB[q] = rowB[(2 * q + 1) * STROW + lane];
                    float b0 = rowB[(2 * q) * STROW + 32];
                    ebB[q] = rowB[(2 * q + 1) * STROW + 32];
                    float pe = __shfl_up_sync(0xffffffffu, e0, 1);
                    if (lane == 0) pe = rowB[(2 * q) * STROW + 33];
                    eeA[q] = e0; ebA[q] = b0; peA[q] = pe;
                    wP[q] = lse2(b0, pe);
                    wR[q] = lse2(e0, b0);
                    wS[q] = lse3v(sk ? e0 : NEGF, b0, sk ? pe : NEGF);
                }
#pragma unroll
                for (int q = 0; q < 4; q++) {
                    const int t = tB + 2 * q;
                    float p1 = __shfl_up_sync(0xffffffffu, A1, 1);
                    float p0 = __shfl_up_sync(0xffffffffu, A0, 1);
                    float q1s = __shfl_up_sync(0xffffffffu, A1, 2);
                    const int slot = (((tB - 1) >> 1) + q) & 31;
                    const float* rg = ringC + ((size_t)wp * 32 + slot) * 4;
                    float rA0 = rg[0], rA1 = rg[1], rB1 = rg[2];   // broadcast
                    if (lane == 0) {
                        p1 = w ? rA1 : NEGF;
                        p0 = w ? rA0 : NEGF;
                        q1s = w ? rB1 : NEGF;
                    }
                    if (lane == 1) q1s = w ? rA1 : NEGF;
                    if (t + 1 < len) {
                        float n0 = lse4(A0 + ebA[q], p1 + wP[q], p0 + peA[q],
                                        skp ? (q1s + peA[q]) : NEGF) + ebB[q];
                        float n1 = lse5(A1 + eeA[q], A0 + wR[q], p1 + wS[q],
                                        sk ? (p0 + peA[q]) : NEGF,
                                        (sk && skp) ? (q1s + peA[q]) : NEGF) + eeB[q];
                        if (w == 7) {
                            float n4 = lse4(A4 + ebA[q], A1 + wR[q], A0 + eeA[q],
                                            sk ? (p1 + eeA[q]) : NEGF) + ebB[q];
                            A4 = (lane == 31) ? n4 : A4;
                        }
                        if (lane >= 30) {
                            float* rw = ringC + ((size_t)w * 32 + (((t + 1) >> 1) & 31)) * 4;
                            if (lane == 31) { rw[0] = n0; rw[1] = n1; }
                            else rw[2] = n1;
                        }
                        A0 = n0; A1 = n1;
                    } else if (t < len) {
                        float n0 = lse2(A0, p1) + ebA[q];
                        float n1 = lse3v(A1, A0, sk ? p1 : NEGF) + eeA[q];
                        if (w == 7) {
                            float n4 = lse2(A4, A1) + ebA[q];
                            A4 = (lane == 31) ? n4 : A4;
                        }
                        A0 = n0; A1 = n1;
                    }
                }
            }
            buf++; if (buf >= 3) buf -= 3;
            __syncthreads();
        }

        actc[2 * tid + 0] = A0;
        actc[2 * tid + 1] = A1;
        if (tid == 255) actc[512] = A4;
        __syncthreads();
        if (tid == 0) {
            int tl = tg_len[b];
            float aL = actc[2 * tl];
            float aP = actc[2 * tl - 1];
            float m = fmaxf(aL, aP);
            float ll = m + __logf(__expf(aL - m) + __expf(aP - m));
            g_loss[b] = -ll / (float)tl;
        }
    }
}

// ---------------- Kernel 5: reduction ----------------
__global__ void reduce_kernel(float* __restrict__ out) {
    const int tid = threadIdx.x;
    float v = g_loss[tid];
#pragma unroll
    for (int o = 16; o > 0; o >>= 1) v += __shfl_down_sync(0xffffffffu, v, o);
    __shared__ float ws[4];
    if ((tid & 31) == 0) ws[tid >> 5] = v;
    __syncthreads();
    if (tid == 0) out[0] = (ws[0] + ws[1] + ws[2] + ws[3]) * (1.f / (float)NB);
}

extern "C" void kernel_launch(void* const* d_in, const int* in_sizes, int n_in,
                              void* d_out, int out_size) {
    const float* lp  = (const float*)d_in[0];
    const float* fm  = (const float*)d_in[1];
    const int*   tgt = (const int*)  d_in[2];
    const int*   il  = (const int*)  d_in[3];
    const int*   tl  = (const int*)  d_in[4];
    float* out = (float*)d_out;

    // stage 8*864 + ringS 8*64*4 floats = 35,840 B (sdtw side max)
    const int dynSmem = (8 * STQ + 8 * 64 * 4) * 4;
    cudaFuncSetAttribute(main_kernel, cudaFuncAttributeMaxDynamicSharedMemorySize, dynSmem);

    prep_kernel<<<512, 256>>>(lp, fm);
    em_kernel<<<1024, 256>>>(lp, tgt);
    cost_kernel<<<dim3(16, 64), 256>>>(fm, tgt);
    main_kernel<<<2 * NB, 256, dynSmem>>>(tgt, il, tl);
    reduce_kernel<<<1, 128>>>(out);
}

// round 17
// speedup vs baseline: 1.2696x; 1.2256x over previous
#include <cuda_runtime.h>
#include <cstddef>
#include <cstdint>

#define NB 64
#define NT 1024
#define NV 256
#define NS 256
#define ND 24
#define NL 513          // 2*NS+1
#define DGA 1344        // allocated dg rows per batch
#define EMW 260         // em row: [0..255]=labels, [256]=blank, pad to 260
#define KPH 16          // steps per phase
#define MLAG_S 3        // sdtw inter-warp lag (phases): (m-1)*16 >= 31 -> m=3
#define NPH_S 87        // sdtw phases: 66 active + 3*7 lag
#define NPH_C 71        // ctc phases: 64 active + 7 lag
#define STROW 36        // staged row: 32 data floats (+blank at [32] for ctc), padded
#define STQ (3 * KPH * STROW)   // per-warp stage floats (3 buffers)
#define GAMMA 0.1f
#define NEGF (-1e10f)
#define BIGF (1e10f)

// Scratch (no allocation allowed)
__device__ float g_pred[NB * NT * ND];            // predicted features (B,T,D)
__device__ float g_cost[(size_t)NB * DGA * NS];   // cost, [b][dg][j], dg=i+j+2
__device__ float g_em[(size_t)NB * NT * EMW];     // emissions per label + blank
__device__ float g_loss[2 * NB];                  // [0..63] ctc, [64..127] sdtw

// mn <= md <= mx with pure min/max (no cancellation)
__device__ __forceinline__ void sort3(float a, float b, float c,
                                      float& mn, float& md, float& mx) {
    float t1 = fminf(a, b);
    float t2 = fmaxf(a, b);
    mn = fminf(t1, c);
    mx = fmaxf(t2, c);
    md = fmaxf(t1, fminf(t2, c));
}

__device__ __forceinline__ void cpAsync16(uint32_t dst, const void* src) {
    asm volatile("cp.async.cg.shared.global [%0], [%1], 16;" :: "r"(dst), "l"(src));
}
__device__ __forceinline__ void cpAsync4(uint32_t dst, const void* src) {
    asm volatile("cp.async.ca.shared.global [%0], [%1], 4;" :: "r"(dst), "l"(src));
}
__device__ __forceinline__ void cpCommit() {
    asm volatile("cp.async.commit_group;" ::: "memory");
}
__device__ __forceinline__ void cpWait2() {
    asm volatile("cp.async.wait_group 2;" ::: "memory");
}

// ----------------------------------------------------------------------------
// Kernel 1: pred = exp(log_probs) @ fm   (65536 x 256) @ (256 x 24)
// ----------------------------------------------------------------------------
__global__ __launch_bounds__(256) void prep_kernel(const float* __restrict__ lp,
                                                   const float* __restrict__ fm) {
    __shared__ float eS[64 * 129];
    __shared__ float fmS[64 * 25];

    const int tid = threadIdx.x;
    const int row0 = blockIdx.x * 128;
    const int rg = tid >> 3;
    const int dgrp = tid & 7;

    float acc[4][3];
#pragma unroll
    for (int i = 0; i < 4; i++)
#pragma unroll
        for (int j = 0; j < 3; j++) acc[i][j] = 0.f;

    for (int v0 = 0; v0 < NV; v0 += 64) {
        for (int idx = tid; idx < 64 * 24; idx += 256) {
            int v = idx / 24, d = idx - v * 24;
            fmS[v * 25 + d] = fm[(v0 + v) * ND + d];
        }
        for (int idx = tid; idx < 128 * 64; idx += 256) {
            int r = idx >> 6, v = idx & 63;
            eS[v * 129 + r] = __expf(lp[(size_t)(row0 + r) * NV + v0 + v]);
        }
        __syncthreads();

#pragma unroll 4
        for (int v = 0; v < 64; v++) {
            float e0 = eS[v * 129 + rg * 4 + 0];
            float e1 = eS[v * 129 + rg * 4 + 1];
            float e2 = eS[v * 129 + rg * 4 + 2];
            float e3 = eS[v * 129 + rg * 4 + 3];
            float f0 = fmS[v * 25 + dgrp * 3 + 0];
            float f1 = fmS[v * 25 + dgrp * 3 + 1];
            float f2 = fmS[v * 25 + dgrp * 3 + 2];
            acc[0][0] += e0 * f0; acc[0][1] += e0 * f1; acc[0][2] += e0 * f2;
            acc[1][0] += e1 * f0; acc[1][1] += e1 * f1; acc[1][2] += e1 * f2;
            acc[2][0] += e2 * f0; acc[2][1] += e2 * f1; acc[2][2] += e2 * f2;
            acc[3][0] += e3 * f0; acc[3][1] += e3 * f1; acc[3][2] += e3 * f2;
        }
        __syncthreads();
    }

#pragma unroll
    for (int i = 0; i < 4; i++)
#pragma unroll
        for (int j = 0; j < 3; j++)
            g_pred[(size_t)(row0 + rg * 4 + i) * ND + dgrp * 3 + j] = acc[i][j];
}

// ----------------------------------------------------------------------------
// Kernel 2 (fused): blockIdx.x < 16 -> sdtw cost tile; else -> emission chunk.
// Independent workloads co-occupy the machine instead of running serially.
// ----------------------------------------------------------------------------
__global__ __launch_bounds__(256) void cost_em_kernel(const float* __restrict__ lp,
                                                      const float* __restrict__ fm,
                                                      const int* __restrict__ targets) {
    __shared__ float predS[64 * 25];
    __shared__ float qS[256 * 25];
    __shared__ float pn[64];
    __shared__ float qn[256];
    __shared__ int qlab[256];
    __shared__ float rowS[4][256];

    const int tid = threadIdx.x;
    const int b = blockIdx.y;

    if (blockIdx.x < 16) {
        // ================= cost tile (layout [b][dg][j]) =================
        const int i0 = blockIdx.x * 64;

        qlab[tid] = targets[b * NS + tid];
        for (int idx = tid; idx < 64 * 24; idx += 256)
            predS[(idx / 24) * 25 + (idx % 24)] = g_pred[(size_t)(b * NT + i0) * ND + idx];
        __syncthreads();
        for (int idx = tid; idx < 256 * 24; idx += 256) {
            int c = idx / 24, d = idx - c * 24;
            qS[c * 25 + d] = fm[qlab[c] * ND + d];
        }
        __syncthreads();
        if (tid < 64) {
            float s = 0.f;
#pragma unroll
            for (int d = 0; d < ND; d++) { float x = predS[tid * 25 + d]; s += x * x; }
            pn[tid] = s;
        }
        {
            float s = 0.f;
#pragma unroll
            for (int d = 0; d < ND; d++) { float x = qS[tid * 25 + d]; s += x * x; }
            qn[tid] = s;
        }
        __syncthreads();

        const int w = tid >> 5;
        const int lane = tid & 31;
        const int j0 = w * 32;

        float p0[ND], p1[ND];
#pragma unroll
        for (int k = 0; k < ND; k++) {
            p0[k] = predS[lane * 25 + k];
            p1[k] = predS[(lane + 32) * 25 + k];
        }
        const float pn0 = pn[lane], pn1 = pn[lane + 32];
        const size_t cb = (size_t)b * DGA;
        const int D0 = i0 + j0 + 2;

#pragma unroll 4
        for (int c = 0; c < 32; c++) {
            int jc = j0 + ((c - lane) & 31);
            float dot0 = 0.f, dot1 = 0.f;
#pragma unroll
            for (int k = 0; k < ND; k++) {
                float q = qS[jc * 25 + k];
                dot0 += p0[k] * q;
                dot1 += p1[k] * q;
            }
            float qnj = qn[jc];
            int dg0 = D0 + c + ((lane > c) ? 32 : 0);
            g_cost[(cb + dg0) * NS + jc] = pn0 + qnj - 2.f * dot0;
            g_cost[(cb + dg0 + 32) * NS + jc] = pn1 + qnj - 2.f * dot1;
        }
    } else {
        // ========= emission chunk: em[b][t][j]=lp[t][tgt[j]]; [256]=blank =========
        const int t0 = (blockIdx.x - 16) << 6;

        qlab[tid] = targets[b * NS + tid];
        const float* lpb = lp + ((size_t)b * NT + t0) * NV;
        float* emb = g_em + ((size_t)b * NT + t0) * EMW;
        __syncthreads();

        for (int tt = 0; tt < 64; tt += 4) {
#pragma unroll
            for (int r = 0; r < 4; r++)
                rowS[r][tid] = lpb[(size_t)(tt + r) * NV + tid];
            __syncthreads();
#pragma unroll
            for (int r = 0; r < 4; r++)
                emb[(size_t)(tt + r) * EMW + tid] = rowS[r][qlab[tid]];
            if (tid < 4) emb[(size_t)(tt + tid) * EMW + 256] = rowS[tid][0];
            __syncthreads();
        }
    }
}

// ----------------------------------------------------------------------------
// Kernel 3 (fused DP — R11 config: 8 warps/block = 2 per SMSP):
//   blocks 0..63  -> soft-DTW : 1 col/thread, lag m=3
//   blocks 64..127-> CTC      : 2 states/thread, lag m=1
// cp.async per-warp staging; phase-skewed barriers; rings 64 deep.
// ----------------------------------------------------------------------------
extern __shared__ float smf[];

__global__ __launch_bounds__(256) void main_kernel(const int* __restrict__ targets,
                                                   const int* __restrict__ in_len,
                                                   const int* __restrict__ tg_len) {
    float* stage = smf;                                  // [8][3][KPH][STROW]
    const int tid = threadIdx.x;                         // 0..255
    const int lane = tid & 31;
    const int w = tid >> 5;                              // 0..7
    const int bid = blockIdx.x;

    const uint32_t stageU =
        (uint32_t)__cvta_generic_to_shared(stage) + (uint32_t)(w * STQ) * 4u;
    const int rsel = lane >> 3;            // 0..3 : row sub-group
    const int csel = lane & 7;             // 16B chunk within 128B row

    if (bid < NB) {
        // ======================= soft-DTW =======================
        float* bndR = smf + 8 * STQ;                     // [8][1312]
        const int b = bid;
        const int s0 = 32 * w + 2;                       // warp's first diagonal
        const int jj = tid + 1;                          // column (1-based)
        const int wp = (w == 0) ? 0 : (w - 1);

        for (int idx = tid; idx < 8 * 1312; idx += 256) bndR[idx] = BIGF;

        auto stageS = [&](int buf, int dgStart) {
#pragma unroll
            for (int r = 0; r < 4; r++) {
                int row = 4 * r + rsel;
                int dgr = dgStart + row;
                dgr = (dgr < 0) ? 0 : ((dgr > DGA - 1) ? DGA - 1 : dgr);
                uint32_t off = (uint32_t)((buf * KPH + row) * STROW + csel * 4) * 4u;
                cpAsync16(stageU + off,
                          g_cost + ((size_t)b * DGA + dgr) * NS + 32 * w + csel * 4);
            }
            cpCommit();
        };

        stageS(0, s0 + (0 - MLAG_S * w) * KPH);
        stageS(1, s0 + (1 - MLAG_S * w) * KPH);
        __syncthreads();                                 // bndR init visible

        float Rp = BIGF;
        float r3c = (tid == 0) ? 0.f : BIGF;

        int buf = 0;
        for (int p = 0; p < NPH_S; p++) {
            int bufN = buf + 2; if (bufN >= 3) bufN -= 3;
            stageS(bufN, s0 + (p + 2 - MLAG_S * w) * KPH);
            cpWait2();
            __syncwarp();
            const int prel = p - MLAG_S * w;
            if (prel >= 0 && prel <= 65) {
                const int stB = prel * KPH;
                const float* rowB = stage + w * STQ + buf * KPH * STROW + lane;
#pragma unroll
                for (int k = 0; k < KPH; k++) {
                    const int dg = s0 + stB + k;
                    float c = rowB[k * STROW];
                    float r2 = __shfl_up_sync(0xffffffffu, Rp, 1);
                    float bnd = bndR[wp * 1312 + dg - 1];          // broadcast LDS
                    r2 = (lane == 0) ? ((w == 0) ? BIGF : bnd) : r2;
                    float mn, md, mx;
                    sort3(Rp, r2, r3c, mn, md, mx);
                    float sv = 1.f + __expf((mn - md) * 10.f) + __expf((mn - mx) * 10.f);
                    const int i = dg - jj;
                    float Rn = (i >= 1 && i <= NT) ? (c + mn - GAMMA * __logf(sv)) : BIGF;
                    if (lane == 31) bndR[w * 1312 + dg] = Rn;
                    if (dg == NT + NS && tid == 255) g_loss[NB + b] = Rn;
                    r3c = r2;
                    Rp = Rn;
                }
            }
            buf++; if (buf >= 3) buf -= 3;
            __syncthreads();
        }
    } else {
        // ======================= CTC forward =======================
        float* ringT = smf + 8 * STQ;                    // [8][64]
        float* actc = ringT + 8 * 64;                    // [513]
        const int b = bid - NB;
        const int wp = (w == 0) ? 0 : (w - 1);
        // thread tid owns states 2tid (even/blank-type), 2tid+1 (odd/label tid);
        // tid 255 (w7 lane31) also owns state 512.
        bool skip = false;
        if (tid > 0) skip = (targets[b * NS + tid] != targets[b * NS + tid - 1]);
        const float* em = g_em + (size_t)b * NT * EMW;
        const int len = in_len[b];

        auto stageC = [&](int buf, int tStart) {
#pragma unroll
            for (int r = 0; r < 4; r++) {
                int row = 4 * r + rsel;
                int tr = tStart + row;
                tr = (tr < 0) ? 0 : ((tr > NT - 1) ? NT - 1 : tr);
                uint32_t off = (uint32_t)((buf * KPH + row) * STROW + csel * 4) * 4u;
                cpAsync16(stageU + off, em + (size_t)tr * EMW + 32 * w + csel * 4);
            }
            if (lane < KPH) {                             // blank per row
                int tr = tStart + lane;
                tr = (tr < 0) ? 0 : ((tr > NT - 1) ? NT - 1 : tr);
                cpAsync4(stageU + (uint32_t)((buf * KPH + lane) * STROW + 32) * 4u,
                         em + (size_t)tr * EMW + 256);
            }
            cpCommit();
        };

        stageC(0, 1 + (0 - w) * KPH);
        stageC(1, 1 + (1 - w) * KPH);

        // t = 0 init: state0 = blank emission, state1 = label0 emission
        float A0 = NEGF, A1 = NEGF, A4 = NEGF;
        if (tid == 0) { A0 = em[256]; A1 = em[0]; }
        if (lane == 31) ringT[w * 64] = A1;               // slot t=0
        __syncthreads();

        int buf = 0;
        for (int p = 0; p < NPH_C; p++) {
            int bufN = buf + 2; if (bufN >= 3) bufN -= 3;
            stageC(bufN, 1 + (p + 2 - w) * KPH);
            cpWait2();
            __syncwarp();
            const int tB = 1 + (p - w) * KPH;
            if (p >= w && tB < len) {
                const float* rowB = stage + w * STQ + buf * KPH * STROW;
#pragma unroll
                for (int k = 0; k < KPH; k++) {
                    const int t = tB + k;
                    float e = rowB[k * STROW + lane];
                    float eb = rowB[k * STROW + 32];
                    float pA1 = __shfl_up_sync(0xffffffffu, A1, 1);
                    float bnd = ringT[wp * 64 + ((t - 1) & 63)];   // broadcast LDS
                    pA1 = (lane == 0) ? ((w == 0) ? NEGF : bnd) : pA1;
                    if (t < len) {                                 // uniform per block
                        // even state 2tid: lse(A0, prevA1) + blank
                        float m0 = fmaxf(A0, pA1);
                        float q0 = m0 + __logf(1.f + __expf(fminf(A0, pA1) - m0)) + eb;
                        // odd state 2tid+1: lse(A1, A0, skip?prevA1:NEG) + label
                        float av = skip ? pA1 : NEGF;
                        float mn, md, mx;
                        sort3(A1, A0, av, mn, md, mx);
                        float q1 = mx + __logf(1.f + __expf(mn - mx) + __expf(md - mx)) + e;
                        // state 512 (even): lse(A4, state511=A1 old) + blank — w7 only
                        if (w == 7) {
                            float m4 = fmaxf(A4, A1);
                            float q4 = m4 + __logf(1.f + __expf(fminf(A4, A1) - m4)) + eb;
                            A4 = (lane == 31) ? q4 : A4;
                        }
                        if (lane == 31) ringT[w * 64 + (t & 63)] = q1;
                        A0 = q0; A1 = q1;
                    }
                }
            }
            buf++; if (buf >= 3) buf -= 3;
            __syncthreads();
        }

        actc[2 * tid + 0] = A0;
        actc[2 * tid + 1] = A1;
        if (tid == 255) actc[512] = A4;
        __syncthreads();
        if (tid == 0) {
            int tl = tg_len[b];
            float aL = actc[2 * tl];
            float aP = actc[2 * tl - 1];
            float m = fmaxf(aL, aP);
            float ll = m + __logf(__expf(aL - m) + __expf(aP - m));
            g_loss[b] = -ll / (float)tl;
        }
    }
}

// ----------------------------------------------------------------------------
// Kernel 4: final reduction to scalar
// ----------------------------------------------------------------------------
__global__ void reduce_kernel(float* __restrict__ out) {
    const int tid = threadIdx.x;      // 128
    float v = g_loss[tid];
#pragma unroll
    for (int o = 16; o > 0; o >>= 1) v += __shfl_down_sync(0xffffffffu, v, o);
    __shared__ float ws[4];
    if ((tid & 31) == 0) ws[tid >> 5] = v;
    __syncthreads();
    if (tid == 0) out[0] = (ws[0] + ws[1] + ws[2] + ws[3]) * (1.f / (float)NB);
}

extern "C" void kernel_launch(void* const* d_in, const int* in_sizes, int n_in,
                              void* d_out, int out_size) {
    const float* lp  = (const float*)d_in[0];  // (B,T,V) f32
    const float* fm  = (const float*)d_in[1];  // (V,D)   f32
    const int*   tgt = (const int*)  d_in[2];  // (B,S)   i32
    const int*   il  = (const int*)  d_in[3];  // (B,)    i32
    const int*   tl  = (const int*)  d_in[4];  // (B,)    i32
    float* out = (float*)d_out;

    // dynamic smem: stage 8*STQ + bndR 8*1312 floats = 97,280 B
    const int dynSmem = (8 * STQ + 8 * 1312) * 4;
    cudaFuncSetAttribute(main_kernel, cudaFuncAttributeMaxDynamicSharedMemorySize, dynSmem);

    prep_kernel<<<512, 256>>>(lp, fm);
    cost_em_kernel<<<dim3(32, 64), 256>>>(lp, fm, tgt);
    main_kernel<<<2 * NB, 256, dynSmem>>>(tgt, il, tl);
    reduce_kernel<<<1, 128>>>(out);
}